// round 1
// baseline (speedup 1.0000x reference)
#include <cuda_runtime.h>
#include <math.h>

#define B_   64
#define T_   256
#define E_   512
#define H_   1024
#define G4H  4096
#define VT   64

// ---------------- scratch (static device allocations; no cudaMalloc) ----------------
__device__ float g_zx_enc[(long)T_ * B_ * G4H];   // 256 MB: encoder x-proj + bias, [t][b][4H]
__device__ float g_dec_xw[VT * G4H];              // 1 MB:  emb_tgt @ W_x + bias, per token
__device__ float g_hbuf[2][B_ * H_];              // encoder h ping-pong
__device__ float g_cbuf[B_ * H_];                 // LSTM cell state
__device__ float g_hs[(long)T_ * B_ * H_];        // 64 MB: decoder hidden outputs [t][b][H]

// ---------------- init: zero h0, c0 ----------------
__global__ void k_init() {
    int idx = blockIdx.x * blockDim.x + threadIdx.x;
    if (idx < B_ * H_) {
        g_cbuf[idx] = 0.f;
        g_hbuf[0][idx] = 0.f;
    }
}

// ---------------- decoder x-projection: dec_xw[v] = emb_tgt[v] @ W_x + b ----------------
// grid (16 colgroups, 64 tokens), block 256
__global__ void k_dec_xproj(const float* __restrict__ emb_tgt,
                            const float* __restrict__ Wl,
                            const float* __restrict__ bias) {
    __shared__ float s_emb[E_];
    int v = blockIdx.y;
    int col = blockIdx.x * 256 + threadIdx.x;
    s_emb[threadIdx.x]       = emb_tgt[v * E_ + threadIdx.x];
    s_emb[256 + threadIdx.x] = emb_tgt[v * E_ + 256 + threadIdx.x];
    __syncthreads();
    float acc = bias[col];
#pragma unroll 8
    for (int k = 0; k < E_; ++k)
        acc += s_emb[k] * Wl[k * G4H + col];
    g_dec_xw[v * G4H + col] = acc;
}

// ---------------- encoder x-projection (gathered GEMM) ----------------
// C[16384,4096] = gather(emb_src, tokens) @ W_x + b ; row rg = t*64 + b
// tile 64x64, K-chunk 32; block 256 threads, 4x4 per thread
__global__ void k_enc_xproj(const int* __restrict__ src,
                            const float* __restrict__ emb,
                            const float* __restrict__ Wl,
                            const float* __restrict__ bias) {
    __shared__ float a_s[64][33];
    __shared__ float b_s[32][64];
    __shared__ int   s_tok[64];
    int tid = threadIdx.x;
    int col0 = blockIdx.x * 64;
    int rg0  = blockIdx.y * 64;
    if (tid < 64) {
        int rg = rg0 + tid;
        int t = rg >> 6, b = rg & 63;
        s_tok[tid] = src[b * T_ + t];
    }
    __syncthreads();

    float acc[4][4] = {};
    int ty = tid >> 4, tx = tid & 15;
    for (int k0 = 0; k0 < E_; k0 += 32) {
#pragma unroll
        for (int i = 0; i < 8; ++i) {
            int idx = i * 256 + tid;
            int r = idx >> 5, kk = idx & 31;
            a_s[r][kk] = emb[s_tok[r] * E_ + k0 + kk];
        }
#pragma unroll
        for (int i = 0; i < 8; ++i) {
            int idx = i * 256 + tid;
            int kk = idx >> 6, c = idx & 63;
            b_s[kk][c] = Wl[(k0 + kk) * G4H + col0 + c];
        }
        __syncthreads();
#pragma unroll
        for (int kk = 0; kk < 32; ++kk) {
            float4 bv = *(const float4*)&b_s[kk][tx * 4];
#pragma unroll
            for (int i = 0; i < 4; ++i) {
                float a = a_s[ty * 4 + i][kk];
                acc[i][0] += a * bv.x; acc[i][1] += a * bv.y;
                acc[i][2] += a * bv.z; acc[i][3] += a * bv.w;
            }
        }
        __syncthreads();
    }
#pragma unroll
    for (int i = 0; i < 4; ++i) {
        int rg = rg0 + ty * 4 + i;
#pragma unroll
        for (int j = 0; j < 4; ++j) {
            int col = col0 + tx * 4 + j;
            g_zx_enc[(long)rg * G4H + col] = acc[i][j] + bias[col];
        }
    }
}

// ---------------- one LSTM time step (fused z-GEMM + gates + state update) ----------------
// grid 128 CTAs: CTA g owns h-indices j0=g*8 .. j0+7, i.e. z-cols {q*1024 + j0 + jj}
// block 128 threads; GEMM: z[64,32] += h_prev[64,1024] @ W_hh_slice[1024,32]
// mode 0 = encoder (zx from g_zx_enc[t]); mode 1 = decoder (zx = g_dec_xw[token])
__global__ void k_lstm_step(const float* __restrict__ Wl,
                            const int* __restrict__ tgt,
                            int t, int mode) {
    __shared__ float h_s[B_][65];     // reused as zs[b][c] after GEMM
    __shared__ float ws[64][32];
    __shared__ int   s_tok[B_];

    const float* hp; float* hn; const float* zx = nullptr;
    if (mode == 0) {
        hp = g_hbuf[t & 1];
        hn = g_hbuf[(t + 1) & 1];
        zx = g_zx_enc + (long)t * B_ * G4H;
    } else {
        hp = (t == 0) ? g_hbuf[0] : (g_hs + (long)(t - 1) * B_ * H_);
        hn = g_hs + (long)t * B_ * H_;
    }

    int tid = threadIdx.x;
    int j0 = blockIdx.x * 8;
    if (mode == 1 && tid < B_) s_tok[tid] = tgt[tid * T_ + t];
    __syncthreads();

    float acc[4][4] = {};
    int ty = tid >> 3, tx = tid & 7;   // ty: 0..15 (4 b-rows each), tx: 0..7 (4 cols each)

    for (int k0 = 0; k0 < H_; k0 += 64) {
#pragma unroll
        for (int i = 0; i < 32; ++i) {
            int idx = i * 128 + tid;
            int b = idx >> 6, kk = idx & 63;
            h_s[b][kk] = hp[b * H_ + k0 + kk];
        }
#pragma unroll
        for (int i = 0; i < 16; ++i) {
            int idx = i * 128 + tid;
            int kk = idx >> 5, c = idx & 31;
            ws[kk][c] = Wl[(E_ + k0 + kk) * G4H + ((c >> 3) << 10) + j0 + (c & 7)];
        }
        __syncthreads();
#pragma unroll
        for (int kk = 0; kk < 64; ++kk) {
            float4 wv = *(const float4*)&ws[kk][tx * 4];
#pragma unroll
            for (int i = 0; i < 4; ++i) {
                float a = h_s[ty * 4 + i][kk];
                acc[i][0] += a * wv.x; acc[i][1] += a * wv.y;
                acc[i][2] += a * wv.z; acc[i][3] += a * wv.w;
            }
        }
        __syncthreads();
    }

    // add x-term, stash z into shared (reuse h_s storage; stride 65)
    float* zs = &h_s[0][0];
#pragma unroll
    for (int i = 0; i < 4; ++i) {
        int b = ty * 4 + i;
        const float* zrow = (mode == 1) ? (g_dec_xw + s_tok[b] * G4H) : (zx + b * G4H);
#pragma unroll
        for (int j = 0; j < 4; ++j) {
            int c = tx * 4 + j;
            int colG = ((c >> 3) << 10) + j0 + (c & 7);
            zs[b * 65 + c] = acc[i][j] + zrow[colG];
        }
    }
    __syncthreads();

    // gates: 512 (b,jj) pairs, 4 per thread. layout zs[b][q*8+jj], q = i,j,f,o
#pragma unroll
    for (int l = 0; l < 4; ++l) {
        int p = l * 128 + tid;
        int b = p >> 3, jj = p & 7;
        float zi = zs[b * 65 + jj];
        float zj = zs[b * 65 + 8 + jj];
        float zf = zs[b * 65 + 16 + jj];
        float zo = zs[b * 65 + 24 + jj];
        int cidx = b * H_ + j0 + jj;
        float cold = g_cbuf[cidx];
        float ig = 1.f / (1.f + expf(-zi));
        float fg = 1.f / (1.f + expf(-(zf + 1.0f)));   // forget_bias = 1.0
        float og = 1.f / (1.f + expf(-zo));
        float cn = fg * cold + ig * tanhf(zj);
        g_cbuf[cidx] = cn;
        hn[cidx] = og * tanhf(cn);
    }
}

// ---------------- final projection + softmax ----------------
// logits[rg][v] = hs[rg] @ W_proj[:,v] + b_proj[v]; rg = t*64+b; out[b][t][v]
// block: 32 rows x 64 v, 256 threads (2x4 per thread), K-chunk 32
__global__ void k_proj_softmax(const float* __restrict__ Wp,
                               const float* __restrict__ bp,
                               float* __restrict__ out) {
    __shared__ float h_t[32][33];
    __shared__ float w_t[32][VT];
    __shared__ float ls[32][VT + 1];
    __shared__ float s_inv[32];
    int tid = threadIdx.x;
    int rg0 = blockIdx.x * 32;
    int ty = tid >> 4, tx = tid & 15;   // ty: 16 row-pairs, tx: 16 v-quads
    float acc[2][4] = {};

    for (int k0 = 0; k0 < H_; k0 += 32) {
#pragma unroll
        for (int i = 0; i < 4; ++i) {
            int idx = i * 256 + tid;
            int r = idx >> 5, kk = idx & 31;
            h_t[r][kk] = g_hs[(long)(rg0 + r) * H_ + k0 + kk];
        }
#pragma unroll
        for (int i = 0; i < 8; ++i) {
            int idx = i * 256 + tid;
            int kk = idx >> 6, v = idx & 63;
            w_t[kk][v] = Wp[(k0 + kk) * VT + v];
        }
        __syncthreads();
#pragma unroll
        for (int kk = 0; kk < 32; ++kk) {
            float4 wv = *(const float4*)&w_t[kk][tx * 4];
            float a0 = h_t[ty * 2][kk];
            float a1 = h_t[ty * 2 + 1][kk];
            acc[0][0] += a0 * wv.x; acc[0][1] += a0 * wv.y;
            acc[0][2] += a0 * wv.z; acc[0][3] += a0 * wv.w;
            acc[1][0] += a1 * wv.x; acc[1][1] += a1 * wv.y;
            acc[1][2] += a1 * wv.z; acc[1][3] += a1 * wv.w;
        }
        __syncthreads();
    }
#pragma unroll
    for (int i = 0; i < 2; ++i)
#pragma unroll
        for (int j = 0; j < 4; ++j)
            ls[ty * 2 + i][tx * 4 + j] = acc[i][j] + bp[tx * 4 + j];
    __syncthreads();

    if (tid < 32) {
        float m = -1e30f;
#pragma unroll 8
        for (int v = 0; v < VT; ++v) m = fmaxf(m, ls[tid][v]);
        float s = 0.f;
#pragma unroll 8
        for (int v = 0; v < VT; ++v) { float e = expf(ls[tid][v] - m); ls[tid][v] = e; s += e; }
        s_inv[tid] = 1.f / s;
    }
    __syncthreads();
#pragma unroll
    for (int i = 0; i < 8; ++i) {
        int idx = i * 256 + tid;
        int r = idx >> 6, v = idx & 63;
        int rg = rg0 + r;
        int t = rg >> 6, b = rg & 63;
        out[(b * T_ + t) * VT + v] = ls[r][v] * s_inv[r];
    }
}

// ---------------- launch ----------------
extern "C" void kernel_launch(void* const* d_in, const int* in_sizes, int n_in,
                              void* d_out, int out_size) {
    const int*   src     = (const int*)d_in[0];
    const int*   tgt     = (const int*)d_in[1];
    const float* emb_src = (const float*)d_in[2];
    const float* emb_tgt = (const float*)d_in[3];
    const float* Wl      = (const float*)d_in[4];
    const float* bl      = (const float*)d_in[5];
    const float* Wp      = (const float*)d_in[6];
    const float* bp      = (const float*)d_in[7];
    float* out = (float*)d_out;
    (void)in_sizes; (void)n_in; (void)out_size;

    k_init<<<(B_ * H_ + 255) / 256, 256>>>();
    k_dec_xproj<<<dim3(G4H / 256, VT), 256>>>(emb_tgt, Wl, bl);
    k_enc_xproj<<<dim3(G4H / 64, (T_ * B_) / 64), 256>>>(src, emb_src, Wl, bl);

    for (int t = 0; t < T_; ++t)
        k_lstm_step<<<128, 128>>>(Wl, nullptr, t, 0);   // encoder
    for (int t = 0; t < T_; ++t)
        k_lstm_step<<<128, 128>>>(Wl, tgt, t, 1);       // decoder

    k_proj_softmax<<<(T_ * B_) / 32, 256>>>(Wp, bp, out);
}

// round 2
// speedup vs baseline: 1.3123x; 1.3123x over previous
#include <cuda_runtime.h>
#include <math.h>
#include <stdint.h>

#define B_   64
#define T_   256
#define E_   512
#define H_   1024
#define G4H  4096
#define VT   64
#define NCTA 128
#define HPAD 132   // padded h-chunk row (floats); 132*4=528B, 16B-aligned

// ---------------- scratch ----------------
__device__ float g_zx_enc[(long)T_ * B_ * G4H];   // encoder x-proj + bias, [t][b][4H]
__device__ float g_dec_xw[VT * G4H];              // emb_tgt @ W_x + bias, per token
__device__ float g_hbuf[2][B_ * H_];              // h ping-pong
__device__ float g_hs[(long)T_ * B_ * H_];        // decoder hidden outputs [t][b][H]
__device__ unsigned g_cnt;                        // grid barrier counter

// ---------------- f32x2 helpers ----------------
__device__ __forceinline__ unsigned long long pack2(float x) {
    unsigned long long r;
    asm("mov.b64 %0, {%1,%1};" : "=l"(r) : "f"(x));
    return r;
}
__device__ __forceinline__ void fma2(unsigned long long& d, unsigned long long a,
                                     unsigned long long b) {
    asm("fma.rn.f32x2 %0, %1, %2, %0;" : "+l"(d) : "l"(a), "l"(b));
}
__device__ __forceinline__ float2 unpack2(unsigned long long v) {
    float2 f;
    asm("mov.b64 {%0,%1}, %2;" : "=f"(f.x), "=f"(f.y) : "l"(v));
    return f;
}
__device__ __forceinline__ void cpasync16(uint32_t dst, const void* src) {
    asm volatile("cp.async.cg.shared.global [%0], [%1], 16;" :: "r"(dst), "l"(src));
}

// ---------------- init ----------------
__global__ void k_init() {
    int idx = blockIdx.x * blockDim.x + threadIdx.x;
    if (idx < B_ * H_) g_hbuf[0][idx] = 0.f;
    if (idx == 0) g_cnt = 0;
}

// ---------------- decoder x-projection ----------------
__global__ void k_dec_xproj(const float* __restrict__ emb_tgt,
                            const float* __restrict__ Wl,
                            const float* __restrict__ bias) {
    __shared__ float s_emb[E_];
    int v = blockIdx.y;
    int col = blockIdx.x * 256 + threadIdx.x;
    s_emb[threadIdx.x]       = emb_tgt[v * E_ + threadIdx.x];
    s_emb[256 + threadIdx.x] = emb_tgt[v * E_ + 256 + threadIdx.x];
    __syncthreads();
    float acc = bias[col];
#pragma unroll 8
    for (int k = 0; k < E_; ++k)
        acc += s_emb[k] * Wl[k * G4H + col];
    g_dec_xw[v * G4H + col] = acc;
}

// ---------------- encoder x-projection (gathered GEMM, FFMA2) ----------------
__global__ void k_enc_xproj(const int* __restrict__ src,
                            const float* __restrict__ emb,
                            const float* __restrict__ Wl,
                            const float* __restrict__ bias) {
    __shared__ float a_s[64][33];
    __shared__ float b_s[32][64];
    __shared__ int   s_tok[64];
    int tid = threadIdx.x;
    int col0 = blockIdx.x * 64;
    int rg0  = blockIdx.y * 64;
    if (tid < 64) {
        int rg = rg0 + tid;
        int t = rg >> 6, b = rg & 63;
        s_tok[tid] = src[b * T_ + t];
    }
    __syncthreads();

    unsigned long long acc[4][2] = {};
    int ty = tid >> 4, tx = tid & 15;
    for (int k0 = 0; k0 < E_; k0 += 32) {
#pragma unroll
        for (int i = 0; i < 8; ++i) {
            int idx = i * 256 + tid;
            int r = idx >> 5, kk = idx & 31;
            a_s[r][kk] = emb[s_tok[r] * E_ + k0 + kk];
        }
#pragma unroll
        for (int i = 0; i < 8; ++i) {
            int idx = i * 256 + tid;
            int kk = idx >> 6, c = idx & 63;
            b_s[kk][c] = Wl[(k0 + kk) * G4H + col0 + c];
        }
        __syncthreads();
#pragma unroll
        for (int kk = 0; kk < 32; ++kk) {
            ulonglong2 bv = *(const ulonglong2*)&b_s[kk][tx * 4];
#pragma unroll
            for (int i = 0; i < 4; ++i) {
                unsigned long long pa = pack2(a_s[ty * 4 + i][kk]);
                fma2(acc[i][0], pa, bv.x);
                fma2(acc[i][1], pa, bv.y);
            }
        }
        __syncthreads();
    }
#pragma unroll
    for (int i = 0; i < 4; ++i) {
        int rg = rg0 + ty * 4 + i;
        float2 lo = unpack2(acc[i][0]), hi = unpack2(acc[i][1]);
        int col = col0 + tx * 4;
        float* dst = g_zx_enc + (long)rg * G4H + col;
        dst[0] = lo.x + bias[col + 0];
        dst[1] = lo.y + bias[col + 1];
        dst[2] = hi.x + bias[col + 2];
        dst[3] = hi.y + bias[col + 3];
    }
}

// ---------------- persistent LSTM kernel (all 512 steps) ----------------
// 128 CTAs x 256 threads. CTA g owns h-indices j0=g*8..j0+7 -> z-cols {q*1024+j0+jj}.
// W_hh slice [1024][32] resident in SMEM. Grid barrier per step.
__global__ void __launch_bounds__(256, 1)
k_lstm_persist(const float* __restrict__ Wl, const int* __restrict__ tgt) {
    extern __shared__ float sm[];
    float* ws   = sm;                         // [1024][32]       131072 B
    float* hc   = sm + 32768;                 // [2][64][HPAD]     67584 B
    float* cst  = hc + 2 * 64 * HPAD;         // [512]              2048 B
    float* zbuf = cst + 512;                  // [64][33]           8448 B
    float* sdec = zbuf + 64 * 33;             // [64][32]           8192 B
    int*   stok = (int*)(sdec + 64 * 32);     // [64]                256 B

    int tid = threadIdx.x;
    int cta = blockIdx.x;
    int j0 = cta * 8;
    uint32_t hc_s = (uint32_t)__cvta_generic_to_shared(hc);

    // one-time: W_hh slice + dec_xw slice into SMEM; zero cell state
#pragma unroll 8
    for (int i = 0; i < 128; ++i) {
        int idx = i * 256 + tid;
        int k = idx >> 5, c = idx & 31;
        int gcol = ((c >> 3) << 10) + j0 + (c & 7);
        ws[idx] = Wl[(E_ + k) * G4H + gcol];
    }
#pragma unroll
    for (int i = 0; i < 8; ++i) {
        int idx = i * 256 + tid;
        int v = idx >> 5, c = idx & 31;
        int gcol = ((c >> 3) << 10) + j0 + (c & 7);
        sdec[idx] = g_dec_xw[v * G4H + gcol];
    }
    cst[tid] = 0.f;
    cst[tid + 256] = 0.f;
    __syncthreads();

    int rq = tid >> 3, cq = tid & 7;
    int b0 = rq * 2, c0 = cq * 4;
    int gc0 = ((c0 >> 3) << 10) + j0 + (c0 & 7);

    for (int t = 0; t < 2 * T_; ++t) {
        const float* hp = g_hbuf[t & 1];
        float* hn = g_hbuf[(t + 1) & 1];
        int dec = (t >= T_);
        if (dec && tid < 64) stok[tid] = tgt[tid * T_ + (t - T_)];

        unsigned long long acc00 = 0, acc01 = 0, acc10 = 0, acc11 = 0;

        if (t > 0) {
            // preload chunk 0
#pragma unroll
            for (int i = 0; i < 8; ++i) {
                int idx = i * 256 + tid;
                int row = idx >> 5, seg = idx & 31;
                cpasync16(hc_s + (uint32_t)(row * HPAD + seg * 4) * 4,
                          hp + row * H_ + seg * 4);
            }
            asm volatile("cp.async.commit_group;");
            for (int p = 0; p < 8; ++p) {
                asm volatile("cp.async.wait_group 0;");
                __syncthreads();
                if (p < 7) {
                    int nbuf = (p + 1) & 1;
                    int k0 = (p + 1) * 128;
#pragma unroll
                    for (int i = 0; i < 8; ++i) {
                        int idx = i * 256 + tid;
                        int row = idx >> 5, seg = idx & 31;
                        cpasync16(hc_s + (uint32_t)(nbuf * 64 * HPAD + row * HPAD + seg * 4) * 4,
                                  hp + row * H_ + k0 + seg * 4);
                    }
                    asm volatile("cp.async.commit_group;");
                }
                const float* hb = hc + (p & 1) * 64 * HPAD;
                int kg = p * 128;
#pragma unroll 4
                for (int kk = 0; kk < 128; kk += 2) {
                    float2 a0 = *(const float2*)&hb[b0 * HPAD + kk];
                    float2 a1 = *(const float2*)&hb[(b0 + 1) * HPAD + kk];
                    ulonglong2 w0 = *(const ulonglong2*)&ws[(kg + kk) * 32 + c0];
                    ulonglong2 w1 = *(const ulonglong2*)&ws[(kg + kk + 1) * 32 + c0];
                    unsigned long long pa;
                    pa = pack2(a0.x); fma2(acc00, pa, w0.x); fma2(acc01, pa, w0.y);
                    pa = pack2(a1.x); fma2(acc10, pa, w0.x); fma2(acc11, pa, w0.y);
                    pa = pack2(a0.y); fma2(acc00, pa, w1.x); fma2(acc01, pa, w1.y);
                    pa = pack2(a1.y); fma2(acc10, pa, w1.x); fma2(acc11, pa, w1.y);
                }
            }
        }

        // add x-term, stage z in SMEM
        {
            float2 z00 = unpack2(acc00), z01 = unpack2(acc01);
            float2 z10 = unpack2(acc10), z11 = unpack2(acc11);
            float4 x0, x1;
            if (!dec) {
                x0 = *(const float4*)(g_zx_enc + ((long)t * B_ + b0) * G4H + gc0);
                x1 = *(const float4*)(g_zx_enc + ((long)t * B_ + b0 + 1) * G4H + gc0);
            } else {
                x0 = *(const float4*)(sdec + stok[b0] * 32 + c0);
                x1 = *(const float4*)(sdec + stok[b0 + 1] * 32 + c0);
            }
            float* zr0 = zbuf + b0 * 33 + c0;
            float* zr1 = zbuf + (b0 + 1) * 33 + c0;
            zr0[0] = z00.x + x0.x; zr0[1] = z00.y + x0.y;
            zr0[2] = z01.x + x0.z; zr0[3] = z01.y + x0.w;
            zr1[0] = z10.x + x1.x; zr1[1] = z10.y + x1.y;
            zr1[2] = z11.x + x1.z; zr1[3] = z11.y + x1.w;
        }
        __syncthreads();

        // gates: 512 (b,jj) pairs, 2 per thread
#pragma unroll
        for (int l = 0; l < 2; ++l) {
            int p = l * 256 + tid;
            int b = p >> 3, jj = p & 7;
            float zi = zbuf[b * 33 + jj];
            float zj = zbuf[b * 33 + 8 + jj];
            float zf = zbuf[b * 33 + 16 + jj];
            float zo = zbuf[b * 33 + 24 + jj];
            float cold = cst[p];
            float ig = 1.f / (1.f + expf(-zi));
            float fg = 1.f / (1.f + expf(-(zf + 1.0f)));   // forget_bias
            float og = 1.f / (1.f + expf(-zo));
            float cn = fg * cold + ig * tanhf(zj);
            cst[p] = cn;
            float hv = og * tanhf(cn);
            hn[b * H_ + j0 + jj] = hv;
            if (dec) g_hs[((long)(t - T_) * B_ + b) * H_ + j0 + jj] = hv;
        }

        // grid barrier
        __syncthreads();
        if (tid == 0) {
            __threadfence();
            unsigned target = (unsigned)(t + 1) * NCTA;
            atomicAdd(&g_cnt, 1u);
            while (*((volatile unsigned*)&g_cnt) < target) {}
            __threadfence();
        }
        __syncthreads();
    }
}

// ---------------- final projection + softmax ----------------
__global__ void k_proj_softmax(const float* __restrict__ Wp,
                               const float* __restrict__ bp,
                               float* __restrict__ out) {
    __shared__ float h_t[32][33];
    __shared__ float w_t[32][VT];
    __shared__ float ls[32][VT + 1];
    __shared__ float s_inv[32];
    int tid = threadIdx.x;
    int rg0 = blockIdx.x * 32;
    int ty = tid >> 4, tx = tid & 15;
    float acc[2][4] = {};

    for (int k0 = 0; k0 < H_; k0 += 32) {
#pragma unroll
        for (int i = 0; i < 4; ++i) {
            int idx = i * 256 + tid;
            int r = idx >> 5, kk = idx & 31;
            h_t[r][kk] = g_hs[(long)(rg0 + r) * H_ + k0 + kk];
        }
#pragma unroll
        for (int i = 0; i < 8; ++i) {
            int idx = i * 256 + tid;
            int kk = idx >> 6, v = idx & 63;
            w_t[kk][v] = Wp[(k0 + kk) * VT + v];
        }
        __syncthreads();
#pragma unroll
        for (int kk = 0; kk < 32; ++kk) {
            float4 wv = *(const float4*)&w_t[kk][tx * 4];
            float a0 = h_t[ty * 2][kk];
            float a1 = h_t[ty * 2 + 1][kk];
            acc[0][0] += a0 * wv.x; acc[0][1] += a0 * wv.y;
            acc[0][2] += a0 * wv.z; acc[0][3] += a0 * wv.w;
            acc[1][0] += a1 * wv.x; acc[1][1] += a1 * wv.y;
            acc[1][2] += a1 * wv.z; acc[1][3] += a1 * wv.w;
        }
        __syncthreads();
    }
#pragma unroll
    for (int i = 0; i < 2; ++i)
#pragma unroll
        for (int j = 0; j < 4; ++j)
            ls[ty * 2 + i][tx * 4 + j] = acc[i][j] + bp[tx * 4 + j];
    __syncthreads();

    if (tid < 32) {
        float m = -1e30f;
#pragma unroll 8
        for (int v = 0; v < VT; ++v) m = fmaxf(m, ls[tid][v]);
        float s = 0.f;
#pragma unroll 8
        for (int v = 0; v < VT; ++v) { float e = expf(ls[tid][v] - m); ls[tid][v] = e; s += e; }
        s_inv[tid] = 1.f / s;
    }
    __syncthreads();
#pragma unroll
    for (int i = 0; i < 8; ++i) {
        int idx = i * 256 + tid;
        int r = idx >> 6, v = idx & 63;
        int rg = rg0 + r;
        int t = rg >> 6, b = rg & 63;
        out[(b * T_ + t) * VT + v] = ls[r][v] * s_inv[r];
    }
}

// ---------------- launch ----------------
extern "C" void kernel_launch(void* const* d_in, const int* in_sizes, int n_in,
                              void* d_out, int out_size) {
    const int*   src     = (const int*)d_in[0];
    const int*   tgt     = (const int*)d_in[1];
    const float* emb_src = (const float*)d_in[2];
    const float* emb_tgt = (const float*)d_in[3];
    const float* Wl      = (const float*)d_in[4];
    const float* bl      = (const float*)d_in[5];
    const float* Wp      = (const float*)d_in[6];
    const float* bp      = (const float*)d_in[7];
    float* out = (float*)d_out;
    (void)in_sizes; (void)n_in; (void)out_size;

    const int SMEM_BYTES = (32768 + 2 * 64 * HPAD + 512 + 64 * 33 + 64 * 32) * 4 + 64 * 4;
    cudaFuncSetAttribute(k_lstm_persist, cudaFuncAttributeMaxDynamicSharedMemorySize,
                         SMEM_BYTES);

    k_init<<<(B_ * H_ + 255) / 256, 256>>>();
    k_dec_xproj<<<dim3(G4H / 256, VT), 256>>>(emb_tgt, Wl, bl);
    k_enc_xproj<<<dim3(G4H / 64, (T_ * B_) / 64), 256>>>(src, emb_src, Wl, bl);
    k_lstm_persist<<<NCTA, 256, SMEM_BYTES>>>(Wl, tgt);
    k_proj_softmax<<<(T_ * B_) / 32, 256>>>(Wp, bp, out);
}

// round 3
// speedup vs baseline: 1.3132x; 1.0007x over previous
#include <cuda_runtime.h>
#include <math.h>
#include <stdint.h>

#define B_   64
#define T_   256
#define E_   512
#define H_   1024
#define G4H  4096
#define VT   64
#define NCTA 128
#define HPAD 132   // padded h-chunk row (floats); 132*4=528B, 16B-aligned

// ---------------- scratch ----------------
__device__ float g_zx_enc[(long)T_ * B_ * G4H];   // encoder x-proj + bias, [t][b][4H]
__device__ float g_dec_xw[VT * G4H];              // emb_tgt @ W_x + bias, per token
__device__ float g_hbuf[2][B_ * H_];              // h ping-pong
__device__ float g_hs[(long)T_ * B_ * H_];        // decoder hidden outputs [t][b][H]
__device__ unsigned g_cnt;                        // grid barrier counter

// ---------------- f32x2 helpers ----------------
__device__ __forceinline__ unsigned long long pack2(float x) {
    unsigned long long r;
    asm("mov.b64 %0, {%1,%1};" : "=l"(r) : "f"(x));
    return r;
}
__device__ __forceinline__ void fma2(unsigned long long& d, unsigned long long a,
                                     unsigned long long b) {
    asm("fma.rn.f32x2 %0, %1, %2, %0;" : "+l"(d) : "l"(a), "l"(b));
}
__device__ __forceinline__ float2 unpack2(unsigned long long v) {
    float2 f;
    asm("mov.b64 {%0,%1}, %2;" : "=f"(f.x), "=f"(f.y) : "l"(v));
    return f;
}
__device__ __forceinline__ void cpasync16(uint32_t dst, const void* src) {
    asm volatile("cp.async.cg.shared.global [%0], [%1], 16;" :: "r"(dst), "l"(src));
}

// ---------------- init ----------------
__global__ void k_init() {
    int idx = blockIdx.x * blockDim.x + threadIdx.x;
    if (idx < B_ * H_) g_hbuf[0][idx] = 0.f;
    if (idx == 0) g_cnt = 0;
}

// ---------------- decoder x-projection ----------------
__global__ void k_dec_xproj(const float* __restrict__ emb_tgt,
                            const float* __restrict__ Wl,
                            const float* __restrict__ bias) {
    __shared__ float s_emb[E_];
    int v = blockIdx.y;
    int col = blockIdx.x * 256 + threadIdx.x;
    s_emb[threadIdx.x]       = emb_tgt[v * E_ + threadIdx.x];
    s_emb[256 + threadIdx.x] = emb_tgt[v * E_ + 256 + threadIdx.x];
    __syncthreads();
    float acc = bias[col];
#pragma unroll 8
    for (int k = 0; k < E_; ++k)
        acc += s_emb[k] * Wl[k * G4H + col];
    g_dec_xw[v * G4H + col] = acc;
}

// ---------------- encoder x-projection (gathered GEMM, FFMA2) ----------------
__global__ void k_enc_xproj(const int* __restrict__ src,
                            const float* __restrict__ emb,
                            const float* __restrict__ Wl,
                            const float* __restrict__ bias) {
    __shared__ float a_s[64][33];
    __shared__ float b_s[32][64];
    __shared__ int   s_tok[64];
    int tid = threadIdx.x;
    int col0 = blockIdx.x * 64;
    int rg0  = blockIdx.y * 64;
    if (tid < 64) {
        int rg = rg0 + tid;
        int t = rg >> 6, b = rg & 63;
        s_tok[tid] = src[b * T_ + t];
    }
    __syncthreads();

    unsigned long long acc[4][2] = {};
    int ty = tid >> 4, tx = tid & 15;
    for (int k0 = 0; k0 < E_; k0 += 32) {
#pragma unroll
        for (int i = 0; i < 8; ++i) {
            int idx = i * 256 + tid;
            int r = idx >> 5, kk = idx & 31;
            a_s[r][kk] = emb[s_tok[r] * E_ + k0 + kk];
        }
#pragma unroll
        for (int i = 0; i < 8; ++i) {
            int idx = i * 256 + tid;
            int kk = idx >> 6, c = idx & 63;
            b_s[kk][c] = Wl[(k0 + kk) * G4H + col0 + c];
        }
        __syncthreads();
#pragma unroll
        for (int kk = 0; kk < 32; ++kk) {
            ulonglong2 bv = *(const ulonglong2*)&b_s[kk][tx * 4];
#pragma unroll
            for (int i = 0; i < 4; ++i) {
                unsigned long long pa = pack2(a_s[ty * 4 + i][kk]);
                fma2(acc[i][0], pa, bv.x);
                fma2(acc[i][1], pa, bv.y);
            }
        }
        __syncthreads();
    }
#pragma unroll
    for (int i = 0; i < 4; ++i) {
        int rg = rg0 + ty * 4 + i;
        float2 lo = unpack2(acc[i][0]), hi = unpack2(acc[i][1]);
        int col = col0 + tx * 4;
        float* dst = g_zx_enc + (long)rg * G4H + col;
        dst[0] = lo.x + bias[col + 0];
        dst[1] = lo.y + bias[col + 1];
        dst[2] = hi.x + bias[col + 2];
        dst[3] = hi.y + bias[col + 3];
    }
}

// ---------------- persistent LSTM kernel (all 512 steps) ----------------
// 128 CTAs x 256 threads. CTA g owns h-indices j0=g*8..j0+7 -> z-cols {q*1024+j0+jj}.
// W_hh slice [1024][32] resident in SMEM. Grid barrier per step.
__global__ void __launch_bounds__(256, 1)
k_lstm_persist(const float* __restrict__ Wl, const int* __restrict__ tgt) {
    extern __shared__ float sm[];
    float* ws   = sm;                         // [1024][32]       131072 B
    float* hc   = sm + 32768;                 // [2][64][HPAD]     67584 B
    float* cst  = hc + 2 * 64 * HPAD;         // [512]              2048 B
    float* zbuf = cst + 512;                  // [64][33]           8448 B
    float* sdec = zbuf + 64 * 33;             // [64][32]           8192 B
    int*   stok = (int*)(sdec + 64 * 32);     // [64]                256 B

    int tid = threadIdx.x;
    int cta = blockIdx.x;
    int j0 = cta * 8;
    uint32_t hc_s = (uint32_t)__cvta_generic_to_shared(hc);

    // one-time: W_hh slice + dec_xw slice into SMEM; zero cell state
#pragma unroll 8
    for (int i = 0; i < 128; ++i) {
        int idx = i * 256 + tid;
        int k = idx >> 5, c = idx & 31;
        int gcol = ((c >> 3) << 10) + j0 + (c & 7);
        ws[idx] = Wl[(E_ + k) * G4H + gcol];
    }
#pragma unroll
    for (int i = 0; i < 8; ++i) {
        int idx = i * 256 + tid;
        int v = idx >> 5, c = idx & 31;
        int gcol = ((c >> 3) << 10) + j0 + (c & 7);
        sdec[idx] = g_dec_xw[v * G4H + gcol];
    }
    cst[tid] = 0.f;
    cst[tid + 256] = 0.f;
    __syncthreads();

    int rq = tid >> 3, cq = tid & 7;
    int b0 = rq * 2, c0 = cq * 4;
    int gc0 = ((c0 >> 3) << 10) + j0 + (c0 & 7);

    for (int t = 0; t < 2 * T_; ++t) {
        const float* hp = g_hbuf[t & 1];
        float* hn = g_hbuf[(t + 1) & 1];
        int dec = (t >= T_);
        if (dec && tid < 64) stok[tid] = tgt[tid * T_ + (t - T_)];

        unsigned long long acc00 = 0, acc01 = 0, acc10 = 0, acc11 = 0;

        if (t > 0) {
            // preload chunk 0
#pragma unroll
            for (int i = 0; i < 8; ++i) {
                int idx = i * 256 + tid;
                int row = idx >> 5, seg = idx & 31;
                cpasync16(hc_s + (uint32_t)(row * HPAD + seg * 4) * 4,
                          hp + row * H_ + seg * 4);
            }
            asm volatile("cp.async.commit_group;");
            for (int p = 0; p < 8; ++p) {
                asm volatile("cp.async.wait_group 0;");
                __syncthreads();
                if (p < 7) {
                    int nbuf = (p + 1) & 1;
                    int k0 = (p + 1) * 128;
#pragma unroll
                    for (int i = 0; i < 8; ++i) {
                        int idx = i * 256 + tid;
                        int row = idx >> 5, seg = idx & 31;
                        cpasync16(hc_s + (uint32_t)(nbuf * 64 * HPAD + row * HPAD + seg * 4) * 4,
                                  hp + row * H_ + k0 + seg * 4);
                    }
                    asm volatile("cp.async.commit_group;");
                }
                const float* hb = hc + (p & 1) * 64 * HPAD;
                int kg = p * 128;
#pragma unroll 4
                for (int kk = 0; kk < 128; kk += 2) {
                    float2 a0 = *(const float2*)&hb[b0 * HPAD + kk];
                    float2 a1 = *(const float2*)&hb[(b0 + 1) * HPAD + kk];
                    ulonglong2 w0 = *(const ulonglong2*)&ws[(kg + kk) * 32 + c0];
                    ulonglong2 w1 = *(const ulonglong2*)&ws[(kg + kk + 1) * 32 + c0];
                    unsigned long long pa;
                    pa = pack2(a0.x); fma2(acc00, pa, w0.x); fma2(acc01, pa, w0.y);
                    pa = pack2(a1.x); fma2(acc10, pa, w0.x); fma2(acc11, pa, w0.y);
                    pa = pack2(a0.y); fma2(acc00, pa, w1.x); fma2(acc01, pa, w1.y);
                    pa = pack2(a1.y); fma2(acc10, pa, w1.x); fma2(acc11, pa, w1.y);
                }
            }
        }

        // add x-term, stage z in SMEM
        {
            float2 z00 = unpack2(acc00), z01 = unpack2(acc01);
            float2 z10 = unpack2(acc10), z11 = unpack2(acc11);
            float4 x0, x1;
            if (!dec) {
                x0 = *(const float4*)(g_zx_enc + ((long)t * B_ + b0) * G4H + gc0);
                x1 = *(const float4*)(g_zx_enc + ((long)t * B_ + b0 + 1) * G4H + gc0);
            } else {
                x0 = *(const float4*)(sdec + stok[b0] * 32 + c0);
                x1 = *(const float4*)(sdec + stok[b0 + 1] * 32 + c0);
            }
            float* zr0 = zbuf + b0 * 33 + c0;
            float* zr1 = zbuf + (b0 + 1) * 33 + c0;
            zr0[0] = z00.x + x0.x; zr0[1] = z00.y + x0.y;
            zr0[2] = z01.x + x0.z; zr0[3] = z01.y + x0.w;
            zr1[0] = z10.x + x1.x; zr1[1] = z10.y + x1.y;
            zr1[2] = z11.x + x1.z; zr1[3] = z11.y + x1.w;
        }
        __syncthreads();

        // gates: 512 (b,jj) pairs, 2 per thread
#pragma unroll
        for (int l = 0; l < 2; ++l) {
            int p = l * 256 + tid;
            int b = p >> 3, jj = p & 7;
            float zi = zbuf[b * 33 + jj];
            float zj = zbuf[b * 33 + 8 + jj];
            float zf = zbuf[b * 33 + 16 + jj];
            float zo = zbuf[b * 33 + 24 + jj];
            float cold = cst[p];
            float ig = 1.f / (1.f + expf(-zi));
            float fg = 1.f / (1.f + expf(-(zf + 1.0f)));   // forget_bias
            float og = 1.f / (1.f + expf(-zo));
            float cn = fg * cold + ig * tanhf(zj);
            cst[p] = cn;
            float hv = og * tanhf(cn);
            hn[b * H_ + j0 + jj] = hv;
            if (dec) g_hs[((long)(t - T_) * B_ + b) * H_ + j0 + jj] = hv;
        }

        // grid barrier
        __syncthreads();
        if (tid == 0) {
            __threadfence();
            unsigned target = (unsigned)(t + 1) * NCTA;
            atomicAdd(&g_cnt, 1u);
            while (*((volatile unsigned*)&g_cnt) < target) {}
            __threadfence();
        }
        __syncthreads();
    }
}

// ---------------- final projection + softmax ----------------
__global__ void k_proj_softmax(const float* __restrict__ Wp,
                               const float* __restrict__ bp,
                               float* __restrict__ out) {
    __shared__ float h_t[32][33];
    __shared__ float w_t[32][VT];
    __shared__ float ls[32][VT + 1];
    __shared__ float s_inv[32];
    int tid = threadIdx.x;
    int rg0 = blockIdx.x * 32;
    int ty = tid >> 4, tx = tid & 15;
    float acc[2][4] = {};

    for (int k0 = 0; k0 < H_; k0 += 32) {
#pragma unroll
        for (int i = 0; i < 4; ++i) {
            int idx = i * 256 + tid;
            int r = idx >> 5, kk = idx & 31;
            h_t[r][kk] = g_hs[(long)(rg0 + r) * H_ + k0 + kk];
        }
#pragma unroll
        for (int i = 0; i < 8; ++i) {
            int idx = i * 256 + tid;
            int kk = idx >> 6, v = idx & 63;
            w_t[kk][v] = Wp[(k0 + kk) * VT + v];
        }
        __syncthreads();
#pragma unroll
        for (int kk = 0; kk < 32; ++kk) {
            float4 wv = *(const float4*)&w_t[kk][tx * 4];
            float a0 = h_t[ty * 2][kk];
            float a1 = h_t[ty * 2 + 1][kk];
            acc[0][0] += a0 * wv.x; acc[0][1] += a0 * wv.y;
            acc[0][2] += a0 * wv.z; acc[0][3] += a0 * wv.w;
            acc[1][0] += a1 * wv.x; acc[1][1] += a1 * wv.y;
            acc[1][2] += a1 * wv.z; acc[1][3] += a1 * wv.w;
        }
        __syncthreads();
    }
#pragma unroll
    for (int i = 0; i < 2; ++i)
#pragma unroll
        for (int j = 0; j < 4; ++j)
            ls[ty * 2 + i][tx * 4 + j] = acc[i][j] + bp[tx * 4 + j];
    __syncthreads();

    if (tid < 32) {
        float m = -1e30f;
#pragma unroll 8
        for (int v = 0; v < VT; ++v) m = fmaxf(m, ls[tid][v]);
        float s = 0.f;
#pragma unroll 8
        for (int v = 0; v < VT; ++v) { float e = expf(ls[tid][v] - m); ls[tid][v] = e; s += e; }
        s_inv[tid] = 1.f / s;
    }
    __syncthreads();
#pragma unroll
    for (int i = 0; i < 8; ++i) {
        int idx = i * 256 + tid;
        int r = idx >> 6, v = idx & 63;
        int rg = rg0 + r;
        int t = rg >> 6, b = rg & 63;
        out[(b * T_ + t) * VT + v] = ls[r][v] * s_inv[r];
    }
}

// ---------------- launch ----------------
extern "C" void kernel_launch(void* const* d_in, const int* in_sizes, int n_in,
                              void* d_out, int out_size) {
    const int*   src     = (const int*)d_in[0];
    const int*   tgt     = (const int*)d_in[1];
    const float* emb_src = (const float*)d_in[2];
    const float* emb_tgt = (const float*)d_in[3];
    const float* Wl      = (const float*)d_in[4];
    const float* bl      = (const float*)d_in[5];
    const float* Wp      = (const float*)d_in[6];
    const float* bp      = (const float*)d_in[7];
    float* out = (float*)d_out;
    (void)in_sizes; (void)n_in; (void)out_size;

    const int SMEM_BYTES = (32768 + 2 * 64 * HPAD + 512 + 64 * 33 + 64 * 32) * 4 + 64 * 4;
    cudaFuncSetAttribute(k_lstm_persist, cudaFuncAttributeMaxDynamicSharedMemorySize,
                         SMEM_BYTES);

    k_init<<<(B_ * H_ + 255) / 256, 256>>>();
    k_dec_xproj<<<dim3(G4H / 256, VT), 256>>>(emb_tgt, Wl, bl);
    k_enc_xproj<<<dim3(G4H / 64, (T_ * B_) / 64), 256>>>(src, emb_src, Wl, bl);
    k_lstm_persist<<<NCTA, 256, SMEM_BYTES>>>(Wl, tgt);
    k_proj_softmax<<<(T_ * B_) / 32, 256>>>(Wp, bp, out);
}

// round 5
// speedup vs baseline: 2.3735x; 1.8074x over previous
#include <cuda_runtime.h>
#include <cuda_bf16.h>
#include <math.h>
#include <stdint.h>

#define B_   64
#define T_   256
#define E_   512
#define H_   1024
#define G4H  4096
#define VT   64
#define NCTA 128

__device__ float g_zx_enc[(long)T_ * B_ * G4H];
__device__ float g_dec_xw[VT * G4H];
__device__ __align__(16) __nv_bfloat16 g_hbf[2][2][B_][H_];  // [phase][hi/lo][b][k]
__device__ float g_hs[(long)T_ * B_ * H_];
__device__ unsigned g_cnt;

// ---- SMEM layout (bytes) ----
// W: 2 planes x [32 n][1024 k] bf16, pitch 1032 elem (2064 B). plane = 66048 B.
#define WPITCH 2064
#define WPLANE 66048
#define SM_B   0
// A chunk: 2 planes x [64 b][128 k] bf16, pitch 136 elem (272 B). plane = 17408 B.
#define APITCH 272
#define APLANE 17408
#define ACHUNK 34816
#define SM_A0  132096
#define SM_A1  166912
#define SM_Z   201728       // [64][33] f32 = 8448
#define SM_SDEC 210176      // [64 tok][32] f32 = 8192
#define SM_STOK 218368      // [64] int = 256
#define SM_TOT  218624

__device__ __forceinline__ void cpasync16(uint32_t dst, const void* src) {
    asm volatile("cp.async.cg.shared.global [%0], [%1], 16;" :: "r"(dst), "l"(src));
}
__device__ __forceinline__ void ldsm4(uint32_t* f, uint32_t addr) {
    asm volatile("ldmatrix.sync.aligned.m8n8.x4.shared.b16 {%0,%1,%2,%3}, [%4];"
        : "=r"(f[0]), "=r"(f[1]), "=r"(f[2]), "=r"(f[3]) : "r"(addr));
}
__device__ __forceinline__ void mma16816(float* c, const uint32_t* a,
                                         uint32_t b0, uint32_t b1) {
    asm volatile("mma.sync.aligned.m16n8k16.row.col.f32.bf16.bf16.f32 "
        "{%0,%1,%2,%3}, {%4,%5,%6,%7}, {%8,%9}, {%0,%1,%2,%3};"
        : "+f"(c[0]), "+f"(c[1]), "+f"(c[2]), "+f"(c[3])
        : "r"(a[0]), "r"(a[1]), "r"(a[2]), "r"(a[3]), "r"(b0), "r"(b1));
}

__global__ void k_init() { if (blockIdx.x == 0 && threadIdx.x == 0) g_cnt = 0; }

// ---------------- decoder x-projection ----------------
__global__ void k_dec_xproj(const float* __restrict__ emb_tgt,
                            const float* __restrict__ Wl,
                            const float* __restrict__ bias) {
    __shared__ float s_emb[E_];
    int v = blockIdx.y;
    int col = blockIdx.x * 256 + threadIdx.x;
    s_emb[threadIdx.x]       = emb_tgt[v * E_ + threadIdx.x];
    s_emb[256 + threadIdx.x] = emb_tgt[v * E_ + 256 + threadIdx.x];
    __syncthreads();
    float acc = bias[col];
#pragma unroll 8
    for (int k = 0; k < E_; ++k) acc += s_emb[k] * Wl[k * G4H + col];
    g_dec_xw[v * G4H + col] = acc;
}

// ---------------- encoder x-projection (FFMA2 GEMM) ----------------
__device__ __forceinline__ unsigned long long pack2(float x) {
    unsigned long long r; asm("mov.b64 %0, {%1,%1};" : "=l"(r) : "f"(x)); return r;
}
__device__ __forceinline__ void fma2(unsigned long long& d, unsigned long long a,
                                     unsigned long long b) {
    asm("fma.rn.f32x2 %0, %1, %2, %0;" : "+l"(d) : "l"(a), "l"(b));
}
__device__ __forceinline__ float2 unpack2(unsigned long long v) {
    float2 f; asm("mov.b64 {%0,%1}, %2;" : "=f"(f.x), "=f"(f.y) : "l"(v)); return f;
}

__global__ void k_enc_xproj(const int* __restrict__ src, const float* __restrict__ emb,
                            const float* __restrict__ Wl, const float* __restrict__ bias) {
    __shared__ float a_s[64][33];
    __shared__ float b_s[32][64];
    __shared__ int s_tok[64];
    int tid = threadIdx.x;
    int col0 = blockIdx.x * 64, rg0 = blockIdx.y * 64;
    if (tid < 64) {
        int rg = rg0 + tid;
        s_tok[tid] = src[(rg & 63) * T_ + (rg >> 6)];
    }
    __syncthreads();
    unsigned long long acc[4][2] = {};
    int ty = tid >> 4, tx = tid & 15;
    for (int k0 = 0; k0 < E_; k0 += 32) {
#pragma unroll
        for (int i = 0; i < 8; ++i) {
            int idx = i * 256 + tid;
            a_s[idx >> 5][idx & 31] = emb[s_tok[idx >> 5] * E_ + k0 + (idx & 31)];
        }
#pragma unroll
        for (int i = 0; i < 8; ++i) {
            int idx = i * 256 + tid;
            b_s[idx >> 6][idx & 63] = Wl[(k0 + (idx >> 6)) * G4H + col0 + (idx & 63)];
        }
        __syncthreads();
#pragma unroll
        for (int kk = 0; kk < 32; ++kk) {
            ulonglong2 bv = *(const ulonglong2*)&b_s[kk][tx * 4];
#pragma unroll
            for (int i = 0; i < 4; ++i) {
                unsigned long long pa = pack2(a_s[ty * 4 + i][kk]);
                fma2(acc[i][0], pa, bv.x);
                fma2(acc[i][1], pa, bv.y);
            }
        }
        __syncthreads();
    }
#pragma unroll
    for (int i = 0; i < 4; ++i) {
        int rg = rg0 + ty * 4 + i;
        float2 lo = unpack2(acc[i][0]), hi = unpack2(acc[i][1]);
        int col = col0 + tx * 4;
        float* dst = g_zx_enc + (long)rg * G4H + col;
        dst[0] = lo.x + bias[col];     dst[1] = lo.y + bias[col + 1];
        dst[2] = hi.x + bias[col + 2]; dst[3] = hi.y + bias[col + 3];
    }
}

// ---------------- persistent HMMA LSTM (all 512 steps) ----------------
__global__ void __launch_bounds__(256, 1)
k_lstm_mma(const float* __restrict__ Wl, const int* __restrict__ tgt) {
    extern __shared__ char sm[];
    uint32_t smb = (uint32_t)__cvta_generic_to_shared(sm);
    float* zbuf = (float*)(sm + SM_Z);
    float* sdec = (float*)(sm + SM_SDEC);
    int*   stok = (int*)(sm + SM_STOK);
    int tid = threadIdx.x, wid = tid >> 5, lane = tid & 31;
    int j0 = blockIdx.x * 8;

    // ---- one-time: W hi/lo planes into SMEM ----
#pragma unroll 4
    for (int i = 0; i < 256; ++i) {
        int idx = i * 256 + tid;            // 0..65535 = 2 planes x 32 n x 1024 k
        int pl = idx >> 15;
        int rem = idx & 32767;
        int n = rem >> 10, k = rem & 1023;
        int gcol = ((n >> 3) << 10) + j0 + (n & 7);
        float w = Wl[(E_ + k) * G4H + gcol];
        __nv_bfloat16 hi = __float2bfloat16(w);
        __nv_bfloat16 v = pl ? __float2bfloat16(w - __bfloat162float(hi)) : hi;
        *(__nv_bfloat16*)(sm + SM_B + pl * WPLANE + n * WPITCH + k * 2) = v;
    }
    // ---- one-time: decoder x-term table ----
#pragma unroll
    for (int i = 0; i < 8; ++i) {
        int idx = i * 256 + tid;
        int v = idx >> 5, c = idx & 31;
        sdec[idx] = g_dec_xw[v * G4H + ((c >> 3) << 10) + j0 + (c & 7)];
    }
    __syncthreads();

    // per-lane ldmatrix offsets
    int m0 = (wid & 3) * 16, n0 = (wid >> 2) * 16;
    uint32_t aoff = (uint32_t)((m0 + ((lane >> 3) & 1) * 8 + (lane & 7)) * APITCH +
                               (lane >> 4) * 16);
    uint32_t boff = smb + SM_B +
                    (uint32_t)((n0 + ((lane >> 3) & 1) * 8 + (lane & 7)) * WPITCH +
                               (lane >> 4) * 16);
    uint32_t abase[2] = { smb + SM_A0, smb + SM_A1 };

    float cr[8];
#pragma unroll
    for (int i = 0; i < 8; ++i) cr[i] = 0.f;

    for (int t = 0; t < 2 * T_; ++t) {
        int dec = (t >= T_);
        const __nv_bfloat16* hp = &g_hbf[t & 1][0][0][0];
        if (dec && tid < 64) stok[tid] = tgt[tid * T_ + (t - T_)];

        float acc0[4] = {}, acc1[4] = {};

        if (t > 0) {
            // preload chunk 0 into buf 0
#pragma unroll
            for (int i = 0; i < 8; ++i) {
                int idx = i * 256 + tid;
                int pl = idx >> 10, r = (idx >> 4) & 63, seg = idx & 15;
                cpasync16(abase[0] + (uint32_t)(pl * APLANE + r * APITCH + seg * 16),
                          hp + pl * (B_ * H_) + r * H_ + seg * 8);
            }
            asm volatile("cp.async.commit_group;");

            for (int p = 0; p < 8; ++p) {
                if (p < 7) {
                    int nb = (p + 1) & 1;
#pragma unroll
                    for (int i = 0; i < 8; ++i) {
                        int idx = i * 256 + tid;
                        int pl = idx >> 10, r = (idx >> 4) & 63, seg = idx & 15;
                        cpasync16(abase[nb] + (uint32_t)(pl * APLANE + r * APITCH + seg * 16),
                                  hp + pl * (B_ * H_) + r * H_ + (p + 1) * 128 + seg * 8);
                    }
                    asm volatile("cp.async.commit_group;");
                    asm volatile("cp.async.wait_group 1;");
                } else {
                    asm volatile("cp.async.wait_group 0;");
                }
                __syncthreads();

                uint32_t ab = abase[p & 1] + aoff;
                uint32_t bb = boff + (uint32_t)(p * 256);
#pragma unroll
                for (int kk = 0; kk < 8; ++kk) {
                    uint32_t ah[4], al[4], bh[4], bl[4];
                    ldsm4(ah, ab + kk * 32);
                    ldsm4(al, ab + APLANE + kk * 32);
                    ldsm4(bh, bb + kk * 32);
                    ldsm4(bl, bb + WPLANE + kk * 32);
                    mma16816(acc0, ah, bh[0], bh[2]);
                    mma16816(acc1, ah, bh[1], bh[3]);
                    mma16816(acc0, ah, bl[0], bl[2]);
                    mma16816(acc1, ah, bl[1], bl[3]);
                    mma16816(acc0, al, bh[0], bh[2]);
                    mma16816(acc1, al, bh[1], bh[3]);
                }
                __syncthreads();
            }

            // stage z to SMEM
            int g = lane >> 2, tg = lane & 3;
            float* z0 = zbuf + (m0 + g) * 33;
            float* z1 = zbuf + (m0 + g + 8) * 33;
            z0[n0 + 2 * tg]     = acc0[0]; z0[n0 + 2 * tg + 1]     = acc0[1];
            z1[n0 + 2 * tg]     = acc0[2]; z1[n0 + 2 * tg + 1]     = acc0[3];
            z0[n0 + 8 + 2 * tg] = acc1[0]; z0[n0 + 8 + 2 * tg + 1] = acc1[1];
            z1[n0 + 8 + 2 * tg] = acc1[2]; z1[n0 + 8 + 2 * tg + 1] = acc1[3];
        }
        __syncthreads();

        // gates on warps 0-1 (thread owns batch b, 8 h-indices)
        if (wid < 2) {
            int b = wid * 32 + lane;
            float z[32];
            if (!dec) {
                const float* zx = g_zx_enc + ((long)t * B_ + b) * G4H + j0;
#pragma unroll
                for (int q = 0; q < 4; ++q) {
                    float4 u = *(const float4*)(zx + q * 1024);
                    float4 v = *(const float4*)(zx + q * 1024 + 4);
                    z[q * 8 + 0] = u.x; z[q * 8 + 1] = u.y;
                    z[q * 8 + 2] = u.z; z[q * 8 + 3] = u.w;
                    z[q * 8 + 4] = v.x; z[q * 8 + 5] = v.y;
                    z[q * 8 + 6] = v.z; z[q * 8 + 7] = v.w;
                }
            } else {
                const float* xs = sdec + stok[b] * 32;
#pragma unroll
                for (int n = 0; n < 32; ++n) z[n] = xs[n];
            }
            if (t > 0) {
#pragma unroll
                for (int n = 0; n < 32; ++n) z[n] += zbuf[b * 33 + n];
            }
            float hh[8];
#pragma unroll
            for (int jj = 0; jj < 8; ++jj) {
                float ig = 1.f / (1.f + expf(-z[jj]));
                float fg = 1.f / (1.f + expf(-(z[16 + jj] + 1.0f)));  // forget_bias
                float og = 1.f / (1.f + expf(-z[24 + jj]));
                cr[jj] = fg * cr[jj] + ig * tanhf(z[8 + jj]);
                hh[jj] = og * tanhf(cr[jj]);
            }
            __nv_bfloat16 phi[8], plo[8];
#pragma unroll
            for (int jj = 0; jj < 8; ++jj) {
                phi[jj] = __float2bfloat16(hh[jj]);
                plo[jj] = __float2bfloat16(hh[jj] - __bfloat162float(phi[jj]));
            }
            *(uint4*)&g_hbf[(t + 1) & 1][0][b][j0] = *(uint4*)phi;
            *(uint4*)&g_hbf[(t + 1) & 1][1][b][j0] = *(uint4*)plo;
            if (dec) {
                float* hd = g_hs + ((long)(t - T_) * B_ + b) * H_ + j0;
                *(float4*)hd       = make_float4(hh[0], hh[1], hh[2], hh[3]);
                *(float4*)(hd + 4) = make_float4(hh[4], hh[5], hh[6], hh[7]);
            }
        }

        // grid barrier
        __syncthreads();
        if (tid == 0) {
            __threadfence();
            unsigned target = (unsigned)(t + 1) * NCTA;
            atomicAdd(&g_cnt, 1u);
            while (*((volatile unsigned*)&g_cnt) < target) {}
            __threadfence();
        }
        __syncthreads();
    }
}

// ---------------- final projection + softmax ----------------
__global__ void k_proj_softmax(const float* __restrict__ Wp, const float* __restrict__ bp,
                               float* __restrict__ out) {
    __shared__ float h_t[32][33];
    __shared__ float w_t[32][VT];
    __shared__ float ls[32][VT + 1];
    __shared__ float s_inv[32];
    int tid = threadIdx.x;
    int rg0 = blockIdx.x * 32;
    int ty = tid >> 4, tx = tid & 15;
    float acc[2][4] = {};
    for (int k0 = 0; k0 < H_; k0 += 32) {
#pragma unroll
        for (int i = 0; i < 4; ++i) {
            int idx = i * 256 + tid;
            h_t[idx >> 5][idx & 31] = g_hs[(long)(rg0 + (idx >> 5)) * H_ + k0 + (idx & 31)];
        }
#pragma unroll
        for (int i = 0; i < 8; ++i) {
            int idx = i * 256 + tid;
            w_t[idx >> 6][idx & 63] = Wp[(k0 + (idx >> 6)) * VT + (idx & 63)];
        }
        __syncthreads();
#pragma unroll
        for (int kk = 0; kk < 32; ++kk) {
            float4 wv = *(const float4*)&w_t[kk][tx * 4];
            float a0 = h_t[ty * 2][kk], a1 = h_t[ty * 2 + 1][kk];
            acc[0][0] += a0 * wv.x; acc[0][1] += a0 * wv.y;
            acc[0][2] += a0 * wv.z; acc[0][3] += a0 * wv.w;
            acc[1][0] += a1 * wv.x; acc[1][1] += a1 * wv.y;
            acc[1][2] += a1 * wv.z; acc[1][3] += a1 * wv.w;
        }
        __syncthreads();
    }
#pragma unroll
    for (int i = 0; i < 2; ++i)
#pragma unroll
        for (int j = 0; j < 4; ++j)
            ls[ty * 2 + i][tx * 4 + j] = acc[i][j] + bp[tx * 4 + j];
    __syncthreads();
    if (tid < 32) {
        float m = -1e30f;
#pragma unroll 8
        for (int v = 0; v < VT; ++v) m = fmaxf(m, ls[tid][v]);
        float s = 0.f;
#pragma unroll 8
        for (int v = 0; v < VT; ++v) { float e = expf(ls[tid][v] - m); ls[tid][v] = e; s += e; }
        s_inv[tid] = 1.f / s;
    }
    __syncthreads();
#pragma unroll
    for (int i = 0; i < 8; ++i) {
        int idx = i * 256 + tid;
        int r = idx >> 6, v = idx & 63;
        int rg = rg0 + r;
        out[((rg & 63) * T_ + (rg >> 6)) * VT + v] = ls[r][v] * s_inv[r];
    }
}

extern "C" void kernel_launch(void* const* d_in, const int* in_sizes, int n_in,
                              void* d_out, int out_size) {
    const int*   src     = (const int*)d_in[0];
    const int*   tgt     = (const int*)d_in[1];
    const float* emb_src = (const float*)d_in[2];
    const float* emb_tgt = (const float*)d_in[3];
    const float* Wl      = (const float*)d_in[4];
    const float* bl      = (const float*)d_in[5];
    const float* Wp      = (const float*)d_in[6];
    const float* bp      = (const float*)d_in[7];
    float* out = (float*)d_out;
    (void)in_sizes; (void)n_in; (void)out_size;

    cudaFuncSetAttribute(k_lstm_mma, cudaFuncAttributeMaxDynamicSharedMemorySize, SM_TOT);

    k_init<<<1, 32>>>();
    k_dec_xproj<<<dim3(G4H / 256, VT), 256>>>(emb_tgt, Wl, bl);
    k_enc_xproj<<<dim3(G4H / 64, (T_ * B_) / 64), 256>>>(src, emb_src, Wl, bl);
    k_lstm_mma<<<NCTA, 256, SM_TOT>>>(Wl, tgt);
    k_proj_softmax<<<(T_ * B_) / 32, 256>>>(Wp, bp, out);
}

// round 6
// speedup vs baseline: 2.6014x; 1.0960x over previous
#include <cuda_runtime.h>
#include <cuda_bf16.h>
#include <math.h>
#include <stdint.h>

#define B_   64
#define T_   256
#define E_   512
#define H_   1024
#define G4H  4096
#define VT   64
#define NCTA 128
#define NTHR 512

__device__ float g_zx_enc[(long)T_ * B_ * G4H];
__device__ float g_dec_xw[VT * G4H];
__device__ __align__(16) __nv_bfloat16 g_hbf[2][2][B_][H_];  // [phase][hi/lo][b][k]
__device__ float g_hs[(long)T_ * B_ * H_];
__device__ unsigned g_cnt;

// ---- SMEM layout (bytes) ----
#define WPITCH 2064            // 1032 bf16 per W row (1024 + 8 pad)
#define WPLANE 66048           // 32 n-rows
#define SM_B   0               // 2 planes (hi/lo) = 132096
#define APITCH 272             // 136 bf16 per A row (128 + 8 pad)
#define APLANE 17408           // 64 b-rows
#define SM_A0  132096          // 2 planes = 34816
#define SM_A1  166912
#define SM_Z   201728          // 2 K-half planes x [64][34] f32 = 17408
#define ZPLANE 8704
#define SM_SDEC 219136         // [64 tok][32] f32 = 8192
#define SM_STOK 227328         // [64] int = 256
#define SM_TOT  227584

__device__ __forceinline__ void cpasync16(uint32_t dst, const void* src) {
    asm volatile("cp.async.cg.shared.global [%0], [%1], 16;" :: "r"(dst), "l"(src));
}
__device__ __forceinline__ void ldsm4(uint32_t* f, uint32_t addr) {
    asm volatile("ldmatrix.sync.aligned.m8n8.x4.shared.b16 {%0,%1,%2,%3}, [%4];"
        : "=r"(f[0]), "=r"(f[1]), "=r"(f[2]), "=r"(f[3]) : "r"(addr));
}
__device__ __forceinline__ void mma16816(float* c, const uint32_t* a,
                                         uint32_t b0, uint32_t b1) {
    asm volatile("mma.sync.aligned.m16n8k16.row.col.f32.bf16.bf16.f32 "
        "{%0,%1,%2,%3}, {%4,%5,%6,%7}, {%8,%9}, {%0,%1,%2,%3};"
        : "+f"(c[0]), "+f"(c[1]), "+f"(c[2]), "+f"(c[3])
        : "r"(a[0]), "r"(a[1]), "r"(a[2]), "r"(a[3]), "r"(b0), "r"(b1));
}
__device__ __forceinline__ float sigf(float x) {
    return __fdividef(1.f, 1.f + __expf(-x));
}

__global__ void k_init() { if (blockIdx.x == 0 && threadIdx.x == 0) g_cnt = 0; }

// ---------------- decoder x-projection ----------------
__global__ void k_dec_xproj(const float* __restrict__ emb_tgt,
                            const float* __restrict__ Wl,
                            const float* __restrict__ bias) {
    __shared__ float s_emb[E_];
    int v = blockIdx.y;
    int col = blockIdx.x * 256 + threadIdx.x;
    s_emb[threadIdx.x]       = emb_tgt[v * E_ + threadIdx.x];
    s_emb[256 + threadIdx.x] = emb_tgt[v * E_ + 256 + threadIdx.x];
    __syncthreads();
    float acc = bias[col];
#pragma unroll 8
    for (int k = 0; k < E_; ++k) acc += s_emb[k] * Wl[k * G4H + col];
    g_dec_xw[v * G4H + col] = acc;
}

// ---------------- encoder x-projection (FFMA2 GEMM) ----------------
__device__ __forceinline__ unsigned long long pack2(float x) {
    unsigned long long r; asm("mov.b64 %0, {%1,%1};" : "=l"(r) : "f"(x)); return r;
}
__device__ __forceinline__ void fma2(unsigned long long& d, unsigned long long a,
                                     unsigned long long b) {
    asm("fma.rn.f32x2 %0, %1, %2, %0;" : "+l"(d) : "l"(a), "l"(b));
}
__device__ __forceinline__ float2 unpack2(unsigned long long v) {
    float2 f; asm("mov.b64 {%0,%1}, %2;" : "=f"(f.x), "=f"(f.y) : "l"(v)); return f;
}

__global__ void k_enc_xproj(const int* __restrict__ src, const float* __restrict__ emb,
                            const float* __restrict__ Wl, const float* __restrict__ bias) {
    __shared__ float a_s[64][33];
    __shared__ float b_s[32][64];
    __shared__ int s_tok[64];
    int tid = threadIdx.x;
    int col0 = blockIdx.x * 64, rg0 = blockIdx.y * 64;
    if (tid < 64) {
        int rg = rg0 + tid;
        s_tok[tid] = src[(rg & 63) * T_ + (rg >> 6)];
    }
    __syncthreads();
    unsigned long long acc[4][2] = {};
    int ty = tid >> 4, tx = tid & 15;
    for (int k0 = 0; k0 < E_; k0 += 32) {
#pragma unroll
        for (int i = 0; i < 8; ++i) {
            int idx = i * 256 + tid;
            a_s[idx >> 5][idx & 31] = emb[s_tok[idx >> 5] * E_ + k0 + (idx & 31)];
        }
#pragma unroll
        for (int i = 0; i < 8; ++i) {
            int idx = i * 256 + tid;
            b_s[idx >> 6][idx & 63] = Wl[(k0 + (idx >> 6)) * G4H + col0 + (idx & 63)];
        }
        __syncthreads();
#pragma unroll
        for (int kk = 0; kk < 32; ++kk) {
            ulonglong2 bv = *(const ulonglong2*)&b_s[kk][tx * 4];
#pragma unroll
            for (int i = 0; i < 4; ++i) {
                unsigned long long pa = pack2(a_s[ty * 4 + i][kk]);
                fma2(acc[i][0], pa, bv.x);
                fma2(acc[i][1], pa, bv.y);
            }
        }
        __syncthreads();
    }
#pragma unroll
    for (int i = 0; i < 4; ++i) {
        int rg = rg0 + ty * 4 + i;
        float2 lo = unpack2(acc[i][0]), hi = unpack2(acc[i][1]);
        int col = col0 + tx * 4;
        float* dst = g_zx_enc + (long)rg * G4H + col;
        dst[0] = lo.x + bias[col];     dst[1] = lo.y + bias[col + 1];
        dst[2] = hi.x + bias[col + 2]; dst[3] = hi.y + bias[col + 3];
    }
}

// ---------------- persistent HMMA LSTM (512 threads, K-split) ----------------
__global__ void __launch_bounds__(NTHR, 1)
k_lstm_mma(const float* __restrict__ Wl, const int* __restrict__ tgt) {
    extern __shared__ char sm[];
    uint32_t smb = (uint32_t)__cvta_generic_to_shared(sm);
    float* zp0  = (float*)(sm + SM_Z);
    float* zp1  = (float*)(sm + SM_Z + ZPLANE);
    float* sdec = (float*)(sm + SM_SDEC);
    int*   stok = (int*)(sm + SM_STOK);
    int tid = threadIdx.x, wid = tid >> 5, lane = tid & 31;
    int j0 = blockIdx.x * 8;

    // ---- one-time: W hi/lo planes into SMEM ----
#pragma unroll 4
    for (int i = 0; i < 128; ++i) {
        int idx = i * NTHR + tid;           // 0..65535 = 2 planes x 32 n x 1024 k
        int pl = idx >> 15;
        int rem = idx & 32767;
        int n = rem >> 10, k = rem & 1023;
        int gcol = ((n >> 3) << 10) + j0 + (n & 7);
        float w = Wl[(E_ + k) * G4H + gcol];
        __nv_bfloat16 hi = __float2bfloat16(w);
        __nv_bfloat16 v = pl ? __float2bfloat16(w - __bfloat162float(hi)) : hi;
        *(__nv_bfloat16*)(sm + SM_B + pl * WPLANE + n * WPITCH + k * 2) = v;
    }
    // ---- one-time: decoder x-term table ----
#pragma unroll
    for (int i = 0; i < 4; ++i) {
        int idx = i * NTHR + tid;
        int v = idx >> 5, c = idx & 31;
        sdec[idx] = g_dec_xw[v * G4H + ((c >> 3) << 10) + j0 + (c & 7)];
    }
    __syncthreads();

    // warp tiling: 4 M-tiles x 2 N-tiles x 2 K-halves
    int m0 = (wid & 3) * 16, n0 = ((wid >> 2) & 1) * 16, ks = (wid >> 3) & 1;
    float* zpm = ks ? zp1 : zp0;
    uint32_t aoff = (uint32_t)((m0 + ((lane >> 3) & 1) * 8 + (lane & 7)) * APITCH +
                               (lane >> 4) * 16);
    uint32_t boff = smb + SM_B +
                    (uint32_t)((n0 + ((lane >> 3) & 1) * 8 + (lane & 7)) * WPITCH +
                               (lane >> 4) * 16);
    uint32_t abase[2] = { smb + SM_A0, smb + SM_A1 };

    // gate-thread state (threads 0..127): thread owns (b = tid>>1, jj0 = (tid&1)*4)
    int gb = tid >> 1, gjj = (tid & 1) * 4;
    float cr[4] = {0.f, 0.f, 0.f, 0.f};

    for (int t = 0; t < 2 * T_; ++t) {
        int dec = (t >= T_);
        const __nv_bfloat16* hp = &g_hbf[t & 1][0][0][0];
        if (dec && tid < 64) stok[tid] = tgt[tid * T_ + (t - T_)];

        float acc0[4] = {}, acc1[4] = {};

        if (t > 0) {
            // preload chunk 0
#pragma unroll
            for (int i = 0; i < 4; ++i) {
                int idx = i * NTHR + tid;
                int pl = idx >> 10, r = (idx >> 4) & 63, seg = idx & 15;
                cpasync16(abase[0] + (uint32_t)(pl * APLANE + r * APITCH + seg * 16),
                          hp + pl * (B_ * H_) + r * H_ + seg * 8);
            }
            asm volatile("cp.async.commit_group;");

            for (int p = 0; p < 8; ++p) {
                if (p < 7) {
                    int nb = (p + 1) & 1;
#pragma unroll
                    for (int i = 0; i < 4; ++i) {
                        int idx = i * NTHR + tid;
                        int pl = idx >> 10, r = (idx >> 4) & 63, seg = idx & 15;
                        cpasync16(abase[nb] + (uint32_t)(pl * APLANE + r * APITCH + seg * 16),
                                  hp + pl * (B_ * H_) + r * H_ + (p + 1) * 128 + seg * 8);
                    }
                    asm volatile("cp.async.commit_group;");
                    asm volatile("cp.async.wait_group 1;");
                } else {
                    asm volatile("cp.async.wait_group 0;");
                }
                __syncthreads();

                uint32_t ab = abase[p & 1] + aoff;
                uint32_t bb = boff + (uint32_t)(p * 256);
#pragma unroll
                for (int i = 0; i < 4; ++i) {
                    uint32_t off = (uint32_t)((ks * 4 + i) * 32);
                    uint32_t ah[4], al[4], bh[4], bl[4];
                    ldsm4(ah, ab + off);
                    ldsm4(al, ab + APLANE + off);
                    ldsm4(bh, bb + off);
                    ldsm4(bl, bb + WPLANE + off);
                    mma16816(acc0, ah, bh[0], bh[2]);
                    mma16816(acc1, ah, bh[1], bh[3]);
                    mma16816(acc0, ah, bl[0], bl[2]);
                    mma16816(acc1, ah, bl[1], bl[3]);
                    mma16816(acc0, al, bh[0], bh[2]);
                    mma16816(acc1, al, bh[1], bh[3]);
                }
                __syncthreads();
            }

            // stage partial z into this K-half's plane
            int g = lane >> 2, tg = lane & 3;
            float* z0 = zpm + (m0 + g) * 34;
            float* z1 = zpm + (m0 + g + 8) * 34;
            z0[n0 + 2 * tg]     = acc0[0]; z0[n0 + 2 * tg + 1]     = acc0[1];
            z1[n0 + 2 * tg]     = acc0[2]; z1[n0 + 2 * tg + 1]     = acc0[3];
            z0[n0 + 8 + 2 * tg] = acc1[0]; z0[n0 + 8 + 2 * tg + 1] = acc1[1];
            z1[n0 + 8 + 2 * tg] = acc1[2]; z1[n0 + 8 + 2 * tg + 1] = acc1[3];
        }
        __syncthreads();

        // gates on 128 threads: (b, 4 h-indices)
        if (tid < 128) {
            float zv[4][4];
            if (!dec) {
                const float* zx = g_zx_enc + ((long)t * B_ + gb) * G4H + j0 + gjj;
#pragma unroll
                for (int q = 0; q < 4; ++q)
                    *(float4*)zv[q] = *(const float4*)(zx + q * 1024);
            } else {
                const float* xs = sdec + stok[gb] * 32 + gjj;
#pragma unroll
                for (int q = 0; q < 4; ++q)
                    *(float4*)zv[q] = *(const float4*)(xs + q * 8);
            }
            if (t > 0) {
#pragma unroll
                for (int q = 0; q < 4; ++q)
#pragma unroll
                    for (int l = 0; l < 4; ++l) {
                        int n = q * 8 + gjj + l;
                        zv[q][l] += zp0[gb * 34 + n] + zp1[gb * 34 + n];
                    }
            }
            float hh[4];
#pragma unroll
            for (int l = 0; l < 4; ++l) {
                float ig = sigf(zv[0][l]);
                float fg = sigf(zv[2][l] + 1.0f);    // forget_bias
                float og = sigf(zv[3][l]);
                cr[l] = fg * cr[l] + ig * tanhf(zv[1][l]);
                hh[l] = og * tanhf(cr[l]);
            }
            __nv_bfloat16 phi[4], plo[4];
#pragma unroll
            for (int l = 0; l < 4; ++l) {
                phi[l] = __float2bfloat16(hh[l]);
                plo[l] = __float2bfloat16(hh[l] - __bfloat162float(phi[l]));
            }
            *(uint2*)&g_hbf[(t + 1) & 1][0][gb][j0 + gjj] = *(uint2*)phi;
            *(uint2*)&g_hbf[(t + 1) & 1][1][gb][j0 + gjj] = *(uint2*)plo;
            if (dec) {
                float* hd = g_hs + ((long)(t - T_) * B_ + gb) * H_ + j0 + gjj;
                *(float4*)hd = make_float4(hh[0], hh[1], hh[2], hh[3]);
            }
        }

        // grid barrier
        __syncthreads();
        if (tid == 0) {
            __threadfence();
            unsigned target = (unsigned)(t + 1) * NCTA;
            atomicAdd(&g_cnt, 1u);
            while (*((volatile unsigned*)&g_cnt) < target) {}
            __threadfence();
        }
        __syncthreads();
    }
}

// ---------------- final projection + softmax ----------------
__global__ void k_proj_softmax(const float* __restrict__ Wp, const float* __restrict__ bp,
                               float* __restrict__ out) {
    __shared__ float h_t[32][33];
    __shared__ float w_t[32][VT];
    __shared__ float ls[32][VT + 1];
    __shared__ float s_inv[32];
    int tid = threadIdx.x;
    int rg0 = blockIdx.x * 32;
    int ty = tid >> 4, tx = tid & 15;
    float acc[2][4] = {};
    for (int k0 = 0; k0 < H_; k0 += 32) {
#pragma unroll
        for (int i = 0; i < 4; ++i) {
            int idx = i * 256 + tid;
            h_t[idx >> 5][idx & 31] = g_hs[(long)(rg0 + (idx >> 5)) * H_ + k0 + (idx & 31)];
        }
#pragma unroll
        for (int i = 0; i < 8; ++i) {
            int idx = i * 256 + tid;
            w_t[idx >> 6][idx & 63] = Wp[(k0 + (idx >> 6)) * VT + (idx & 63)];
        }
        __syncthreads();
#pragma unroll
        for (int kk = 0; kk < 32; ++kk) {
            float4 wv = *(const float4*)&w_t[kk][tx * 4];
            float a0 = h_t[ty * 2][kk], a1 = h_t[ty * 2 + 1][kk];
            acc[0][0] += a0 * wv.x; acc[0][1] += a0 * wv.y;
            acc[0][2] += a0 * wv.z; acc[0][3] += a0 * wv.w;
            acc[1][0] += a1 * wv.x; acc[1][1] += a1 * wv.y;
            acc[1][2] += a1 * wv.z; acc[1][3] += a1 * wv.w;
        }
        __syncthreads();
    }
#pragma unroll
    for (int i = 0; i < 2; ++i)
#pragma unroll
        for (int j = 0; j < 4; ++j)
            ls[ty * 2 + i][tx * 4 + j] = acc[i][j] + bp[tx * 4 + j];
    __syncthreads();
    if (tid < 32) {
        float m = -1e30f;
#pragma unroll 8
        for (int v = 0; v < VT; ++v) m = fmaxf(m, ls[tid][v]);
        float s = 0.f;
#pragma unroll 8
        for (int v = 0; v < VT; ++v) { float e = expf(ls[tid][v] - m); ls[tid][v] = e; s += e; }
        s_inv[tid] = 1.f / s;
    }
    __syncthreads();
#pragma unroll
    for (int i = 0; i < 8; ++i) {
        int idx = i * 256 + tid;
        int r = idx >> 6, v = idx & 63;
        int rg = rg0 + r;
        out[((rg & 63) * T_ + (rg >> 6)) * VT + v] = ls[r][v] * s_inv[r];
    }
}

extern "C" void kernel_launch(void* const* d_in, const int* in_sizes, int n_in,
                              void* d_out, int out_size) {
    const int*   src     = (const int*)d_in[0];
    const int*   tgt     = (const int*)d_in[1];
    const float* emb_src = (const float*)d_in[2];
    const float* emb_tgt = (const float*)d_in[3];
    const float* Wl      = (const float*)d_in[4];
    const float* bl      = (const float*)d_in[5];
    const float* Wp      = (const float*)d_in[6];
    const float* bp      = (const float*)d_in[7];
    float* out = (float*)d_out;
    (void)in_sizes; (void)n_in; (void)out_size;

    cudaFuncSetAttribute(k_lstm_mma, cudaFuncAttributeMaxDynamicSharedMemorySize, SM_TOT);

    k_init<<<1, 32>>>();
    k_dec_xproj<<<dim3(G4H / 256, VT), 256>>>(emb_tgt, Wl, bl);
    k_enc_xproj<<<dim3(G4H / 64, (T_ * B_) / 64), 256>>>(src, emb_src, Wl, bl);
    k_lstm_mma<<<NCTA, NTHR, SM_TOT>>>(Wl, tgt);
    k_proj_softmax<<<(T_ * B_) / 32, 256>>>(Wp, bp, out);
}